// round 7
// baseline (speedup 1.0000x reference)
#include <cuda_runtime.h>
#include <cuda_fp16.h>
#include <cstdint>

#define NTILES 1024

__device__ int g_active[NTILES];
__device__ __align__(16) __half g_wt_h[9 * 256 * 256];    // [pos][f][c] fp16 hi
__device__ __align__(16) __half g_wt_l[9 * 256 * 256];    // [pos][f][c] fp16 lo
__device__ __align__(16) __half g_in_h[4 * 224 * 224 * 256];  // input fp16 hi only

// ---------------- helpers ----------------
__device__ __forceinline__ uint32_t smem_to_u32(const void* p) {
    uint32_t a;
    asm("{ .reg .u64 t; cvta.to.shared.u64 t, %1; cvt.u32.u64 %0, t; }" : "=r"(a) : "l"(p));
    return a;
}
__device__ __forceinline__ void ldsm4(uint32_t* r, uint32_t addr) {
    asm volatile("ldmatrix.sync.aligned.m8n8.x4.shared.b16 {%0,%1,%2,%3}, [%4];"
                 : "=r"(r[0]), "=r"(r[1]), "=r"(r[2]), "=r"(r[3]) : "r"(addr));
}
__device__ __forceinline__ void mma16816(float* d, const uint32_t* a, const uint32_t* b) {
    asm volatile(
        "mma.sync.aligned.m16n8k16.row.col.f32.f16.f16.f32 "
        "{%0,%1,%2,%3}, {%4,%5,%6,%7}, {%8,%9}, {%0,%1,%2,%3};"
        : "+f"(d[0]), "+f"(d[1]), "+f"(d[2]), "+f"(d[3])
        : "r"(a[0]), "r"(a[1]), "r"(a[2]), "r"(a[3]), "r"(b[0]), "r"(b[1]));
}
__device__ __forceinline__ void cpasync16(uint32_t dst, const void* src, int sz) {
    asm volatile("cp.async.cg.shared.global [%0], [%1], 16, %2;\n"
                 :: "r"(dst), "l"(src), "r"(sz) : "memory");
}
__device__ __forceinline__ void cpasync16(uint32_t dst, const void* src) {
    asm volatile("cp.async.cg.shared.global [%0], [%1], 16;\n"
                 :: "r"(dst), "l"(src) : "memory");
}
__device__ __forceinline__ void hsplit(float x, unsigned short& h, unsigned short& l) {
    __half hh = __float2half_rn(x);
    __half ll = __float2half_rn(x - __half2float(hh));
    h = __half_as_ushort(hh);
    l = __half_as_ushort(ll);
}

// ---------------- Stage 0 (fused prep) ----------------
__global__ void __launch_bounds__(256)
prep_kernel(const float* __restrict__ in,
            const float* __restrict__ mask,
            const float* __restrict__ wt)
{
    const int b = blockIdx.x;
    const int tid = threadIdx.x;
    if (b < 1024) {
        int n = b >> 8, bi = (b >> 4) & 15, bj = b & 15;
        int j = tid >> 4, i = tid & 15;
        int r = bi * 14 + j - 1;
        int c = bj * 14 + i - 1;
        float v = 0.0f;
        if (r >= 0 && r < 224 && c >= 0 && c < 224) v = mask[(n * 224 + r) * 224 + c];
        __shared__ double s[256];
        s[tid] = (double)v;
        __syncthreads();
        for (int off = 128; off > 0; off >>= 1) {
            if (tid < off) s[tid] += s[tid + off];
            __syncthreads();
        }
        if (tid == 0) g_active[b] = (s[0] > 128.0) ? 1 : 0;
    } else if (b < 1024 + 2304) {
        // weight transpose + hi/lo split: [pos][c][f] -> [pos][f][c]
        int bb = b - 1024;
        int pos = bb >> 8, f = bb & 255, c = tid;
        float x = wt[((size_t)((pos << 8) | c)) * 256 + f];
        unsigned short h, l;
        hsplit(x, h, l);
        size_t di = ((size_t)((pos << 8) | f)) * 256 + c;
        g_wt_h[di] = __ushort_as_half(h);
        g_wt_l[di] = __ushort_as_half(l);
    } else {
        // input fp32 -> fp16 hi (round-to-nearest), vectorized
        size_t idx = (size_t)(b - 3328) * 256 + tid;
        const float4* in4 = reinterpret_cast<const float4*>(in);
        const size_t total4 = 12845056ull;
        const size_t stride = 6144ull * 256ull;
        for (size_t i = idx; i < total4; i += stride) {
            float4 v = in4[i];
            uint2 hp;
            hp.x = (uint32_t)__half_as_ushort(__float2half_rn(v.x))
                 | ((uint32_t)__half_as_ushort(__float2half_rn(v.y)) << 16);
            hp.y = (uint32_t)__half_as_ushort(__float2half_rn(v.z))
                 | ((uint32_t)__half_as_ushort(__float2half_rn(v.w)) << 16);
            *reinterpret_cast<uint2*>(g_in_h + 4 * i) = hp;
        }
    }
}

// ---------------- Stage 1: pipelined implicit-GEMM conv, N=128/CTA, 2-pass ----
// A per stage: 258 rows x 32B (hi only) = 8256 B
// W per stage: 9 pos x 128 f rows x 32B, hi+lo = 73728 B
// XOR swizzle: byte(row, half) = row*32 + ((half ^ ((row>>2)&1)) << 4)
#define OFF_A   0u
#define A_STAGE 8256u
#define OFF_W   16512u
#define W_STAGE 73728u
#define W_LO    36864u
#define SMEM_DYN 163968

__device__ __forceinline__ void issue_stage(uint32_t aBase, uint32_t wBase,
                                            int tid, int n, int r0, int c0,
                                            int fh, int cc)
{
    // A: 512 ops (256 px x 2 halves), hi only
    #pragma unroll
    for (int k = 0; k < 2; k++) {
        int i = tid + (k << 8);
        int px   = i >> 1;
        int half = i & 1;
        int r = r0 + (px >> 4), c = c0 + (px & 15);
        bool ok = ((unsigned)r < 224u) && ((unsigned)c < 224u);
        int rr = ok ? r : 0, cl = ok ? c : 0;
        const void* src = g_in_h + ((((size_t)(n * 224 + rr)) * 224 + cl) * 256
                                    + cc * 16 + half * 8);
        uint32_t dst = aBase + (uint32_t)px * 32u
                     + (uint32_t)((half ^ ((px >> 2) & 1)) << 4);
        cpasync16(dst, src, ok ? 16 : 0);
    }
    // W: 4608 ops (1152 rows x 2 halves x hi/lo)
    #pragma unroll
    for (int k = 0; k < 18; k++) {
        int i = tid + (k << 8);
        int arr = (i >= 2304) ? 1 : 0;
        int j = i - arr * 2304;
        int row = j >> 1, half = j & 1;
        int pos = row >> 7, fl = row & 127;
        const __half* gsrc = arr ? g_wt_l : g_wt_h;
        const void* src = gsrc + (((size_t)(pos * 256 + fh * 128 + fl)) << 8)
                        + cc * 16 + half * 8;
        uint32_t dst = wBase + (uint32_t)arr * W_LO + (uint32_t)row * 32u
                     + (uint32_t)((half ^ ((row >> 2) & 1)) << 4);
        cpasync16(dst, src);
    }
}

__global__ void __launch_bounds__(256, 1)
conv_kernel(const float* __restrict__ bias, float* __restrict__ out)
{
    const int tile = blockIdx.x;
    const int fh   = blockIdx.y;         // 0..1 -> 128 F channels
    const int n = tile >> 8, bi = (tile >> 4) & 15, bj = tile & 15;
    const int tid = threadIdx.x;

    if (!g_active[tile]) {
        float4 z = make_float4(0.f, 0.f, 0.f, 0.f);
        for (int i = tid; i < 196 * 32; i += 256) {
            int px = i >> 5, q = i & 31;
            int oy = px / 14, ox = px - oy * 14;
            size_t o = (((size_t)(n * 224 + bi * 14 + oy)) * 224 + bj * 14 + ox) * 256
                       + fh * 128 + q * 4;
            *reinterpret_cast<float4*>(out + o) = z;
        }
        return;
    }

    extern __shared__ char sm[];
    const uint32_t sb = smem_to_u32(sm);

    const int l   = tid & 31;
    const int wid = tid >> 5;
    const int wm  = wid >> 2;            // 0..1 : M half (112 rows)
    const int wn  = wid & 3;             // 0..3 : 32-F slice within 128

    const int ra0   = wm * 112 + (l & 15);
    const int ahalf = l >> 4;
    const int rw0   = wn * 32 + ((l >> 4) & 1) * 8 + (l & 7);
    const uint32_t woff = (uint32_t)rw0 * 32u
        + (uint32_t)(((((l >> 3) & 1)) ^ ((rw0 >> 2) & 1)) << 4);
    const int rw1 = rw0 + 16;
    const uint32_t woff1 = (uint32_t)rw1 * 32u
        + (uint32_t)(((((l >> 3) & 1)) ^ ((rw1 >> 2) & 1)) << 4);

    const int r0 = bi * 14 - 1;
    const int c0 = bj * 14 - 1;

    // zero the pad rows (rows 256-257, 64B) in both A stages
    if (tid < 32) {
        int s = tid >> 4;
        *reinterpret_cast<uint32_t*>(sm + OFF_A + s * A_STAGE
                                     + 8192 + (tid & 15) * 4) = 0;
    }

    const uint32_t aS[2] = { sb + OFF_A, sb + OFF_A + A_STAGE };
    const uint32_t wS[2] = { sb + OFF_W, sb + OFF_W + W_STAGE };

    float acc[7][16];
    #pragma unroll
    for (int t = 0; t < 7; t++)
        #pragma unroll
        for (int j = 0; j < 16; j++) acc[t][j] = 0.f;

    // prologue: stage 0
    issue_stage(aS[0], wS[0], tid, n, r0, c0, fh, 0);
    asm volatile("cp.async.commit_group;\n" ::: "memory");

    for (int cc = 0; cc < 16; cc++) {
        const int p = cc & 1;
        asm volatile("cp.async.wait_group 0;\n" ::: "memory");
        __syncthreads();
        if (cc < 15) {
            issue_stage(aS[p ^ 1], wS[p ^ 1], tid, n, r0, c0, fh, cc + 1);
            asm volatile("cp.async.commit_group;\n" ::: "memory");
        }

        const uint32_t aB = aS[p];
        const uint32_t wB = wS[p];
        #pragma unroll 1
        for (int pos = 0; pos < 9; pos++) {
            const int ky = pos / 3, kx = pos - ky * 3;
            const int ra = ra0 + ky * 16 + kx;
            const uint32_t aaddr = aB + (uint32_t)ra * 32u
                + (uint32_t)((ahalf ^ ((ra >> 2) & 1)) << 4);
            const uint32_t wbase = wB + (uint32_t)pos * 4096u;

            uint32_t wh[8], wl[8];
            ldsm4(wh,     wbase + woff);
            ldsm4(wh + 4, wbase + woff1);
            ldsm4(wl,     wbase + W_LO + woff);
            ldsm4(wl + 4, wbase + W_LO + woff1);

            uint32_t a[7][4];
            #pragma unroll
            for (int t = 0; t < 7; t++)
                ldsm4(a[t], aaddr + (uint32_t)t * 512u);
            #pragma unroll
            for (int t = 0; t < 7; t++) {
                #pragma unroll
                for (int g = 0; g < 4; g++)
                    mma16816(acc[t] + g * 4, a[t], wh + g * 2);
            }
            #pragma unroll
            for (int t = 0; t < 7; t++) {
                #pragma unroll
                for (int g = 0; g < 4; g++)
                    mma16816(acc[t] + g * 4, a[t], wl + g * 2);
            }
        }
    }

    // ---- epilogue: bias + relu + store ----
    const int fbase = fh * 128 + wn * 32 + (l & 3) * 2;
    float bb[8];
    #pragma unroll
    for (int g = 0; g < 4; g++) {
        bb[g * 2 + 0] = bias[fbase + g * 8];
        bb[g * 2 + 1] = bias[fbase + g * 8 + 1];
    }

    #pragma unroll
    for (int t = 0; t < 7; t++) {
        int m_lo = wm * 112 + t * 16 + (l >> 2);
        #pragma unroll
        for (int h = 0; h < 2; h++) {
            int m = m_lo + h * 8;
            int oy = m >> 4, ox = m & 15;
            if (ox < 14) {
                float* p = out + (((size_t)(n * 224 + bi * 14 + oy)) * 224
                                  + bj * 14 + ox) * 256 + fbase;
                #pragma unroll
                for (int g = 0; g < 4; g++) {
                    float2 v;
                    v.x = fmaxf(acc[t][g * 4 + h * 2 + 0] + bb[g * 2 + 0], 0.f);
                    v.y = fmaxf(acc[t][g * 4 + h * 2 + 1] + bb[g * 2 + 1], 0.f);
                    *reinterpret_cast<float2*>(p + g * 8) = v;
                }
            }
        }
    }
}

extern "C" void kernel_launch(void* const* d_in, const int* in_sizes, int n_in,
                              void* d_out, int out_size) {
    const float* inputs = (const float*)d_in[0];
    const float* mask   = (const float*)d_in[1];
    const float* kernel = (const float*)d_in[2];
    const float* bias   = (const float*)d_in[3];
    float* out = (float*)d_out;

    cudaFuncSetAttribute(conv_kernel, cudaFuncAttributeMaxDynamicSharedMemorySize, SMEM_DYN);

    prep_kernel<<<9472, 256>>>(inputs, mask, kernel);
    dim3 grid(NTILES, 2);
    conv_kernel<<<grid, 256, SMEM_DYN>>>(bias, out);
}

// round 10
// speedup vs baseline: 1.5977x; 1.5977x over previous
#include <cuda_runtime.h>
#include <cuda_fp16.h>
#include <cstdint>

#define NTILES 1024

__device__ int g_active[NTILES];
__device__ __align__(16) __half g_wt_h[9 * 256 * 256];    // [pos][f][c] fp16 hi
__device__ __align__(16) __half g_wt_l[9 * 256 * 256];    // [pos][f][c] fp16 lo
__device__ __align__(16) __half g_in_h[4 * 224 * 224 * 256];  // input fp16 hi only

// ---------------- helpers ----------------
__device__ __forceinline__ uint32_t smem_to_u32(const void* p) {
    uint32_t a;
    asm("{ .reg .u64 t; cvta.to.shared.u64 t, %1; cvt.u32.u64 %0, t; }" : "=r"(a) : "l"(p));
    return a;
}
__device__ __forceinline__ void ldsm4(uint32_t* r, uint32_t addr) {
    asm volatile("ldmatrix.sync.aligned.m8n8.x4.shared.b16 {%0,%1,%2,%3}, [%4];"
                 : "=r"(r[0]), "=r"(r[1]), "=r"(r[2]), "=r"(r[3]) : "r"(addr));
}
__device__ __forceinline__ void mma16816(float* d, const uint32_t* a, const uint32_t* b) {
    asm volatile(
        "mma.sync.aligned.m16n8k16.row.col.f32.f16.f16.f32 "
        "{%0,%1,%2,%3}, {%4,%5,%6,%7}, {%8,%9}, {%0,%1,%2,%3};"
        : "+f"(d[0]), "+f"(d[1]), "+f"(d[2]), "+f"(d[3])
        : "r"(a[0]), "r"(a[1]), "r"(a[2]), "r"(a[3]), "r"(b[0]), "r"(b[1]));
}
__device__ __forceinline__ void cpasync16(uint32_t dst, const void* src, int sz) {
    asm volatile("cp.async.cg.shared.global [%0], [%1], 16, %2;\n"
                 :: "r"(dst), "l"(src), "r"(sz) : "memory");
}
__device__ __forceinline__ void cpasync16(uint32_t dst, const void* src) {
    asm volatile("cp.async.cg.shared.global [%0], [%1], 16;\n"
                 :: "r"(dst), "l"(src) : "memory");
}
__device__ __forceinline__ void hsplit(float x, unsigned short& h, unsigned short& l) {
    __half hh = __float2half_rn(x);
    __half ll = __float2half_rn(x - __half2float(hh));
    h = __half_as_ushort(hh);
    l = __half_as_ushort(ll);
}

// ---------------- Stage 0 (fused prep) ----------------
__global__ void __launch_bounds__(256)
prep_kernel(const float* __restrict__ in,
            const float* __restrict__ mask,
            const float* __restrict__ wt)
{
    const int b = blockIdx.x;
    const int tid = threadIdx.x;
    if (b < 1024) {
        int n = b >> 8, bi = (b >> 4) & 15, bj = b & 15;
        int j = tid >> 4, i = tid & 15;
        int r = bi * 14 + j - 1;
        int c = bj * 14 + i - 1;
        float v = 0.0f;
        if (r >= 0 && r < 224 && c >= 0 && c < 224) v = mask[(n * 224 + r) * 224 + c];
        __shared__ double s[256];
        s[tid] = (double)v;
        __syncthreads();
        for (int off = 128; off > 0; off >>= 1) {
            if (tid < off) s[tid] += s[tid + off];
            __syncthreads();
        }
        if (tid == 0) g_active[b] = (s[0] > 128.0) ? 1 : 0;
    } else if (b < 1024 + 2304) {
        // weight transpose + hi/lo split: [pos][c][f] -> [pos][f][c]
        int bb = b - 1024;
        int pos = bb >> 8, f = bb & 255, c = tid;
        float x = wt[((size_t)((pos << 8) | c)) * 256 + f];
        unsigned short h, l;
        hsplit(x, h, l);
        size_t di = ((size_t)((pos << 8) | f)) * 256 + c;
        g_wt_h[di] = __ushort_as_half(h);
        g_wt_l[di] = __ushort_as_half(l);
    } else {
        // input fp32 -> fp16 hi (round-to-nearest), vectorized
        size_t idx = (size_t)(b - 3328) * 256 + tid;
        const float4* in4 = reinterpret_cast<const float4*>(in);
        const size_t total4 = 12845056ull;
        const size_t stride = 6144ull * 256ull;
        for (size_t i = idx; i < total4; i += stride) {
            float4 v = in4[i];
            uint2 hp;
            hp.x = (uint32_t)__half_as_ushort(__float2half_rn(v.x))
                 | ((uint32_t)__half_as_ushort(__float2half_rn(v.y)) << 16);
            hp.y = (uint32_t)__half_as_ushort(__float2half_rn(v.z))
                 | ((uint32_t)__half_as_ushort(__float2half_rn(v.w)) << 16);
            *reinterpret_cast<uint2*>(g_in_h + 4 * i) = hp;
        }
    }
}

// ---------------- Stage 1: pipelined implicit-GEMM conv, N=64/CTA, 2-pass ----
// A per stage: 258 rows x 32B (hi only) = 8256 B
// W per stage: 9 pos x 64 f rows x 32B, hi+lo = 36864 B
// XOR swizzle: byte(row, half) = row*32 + ((half ^ ((row>>2)&1)) << 4)
#define OFF_A   0u
#define A_STAGE 8256u
#define OFF_W   16512u
#define W_STAGE 36864u
#define W_LO    18432u
#define SMEM_DYN 90240

__device__ __forceinline__ void issue_stage(uint32_t aBase, uint32_t wBase,
                                            int tid, int n, int r0, int c0,
                                            int fq, int cc)
{
    // A: 512 ops (256 px x 2 halves), hi only
    #pragma unroll
    for (int k = 0; k < 2; k++) {
        int i = tid + (k << 8);
        int px   = i >> 1;
        int half = i & 1;
        int r = r0 + (px >> 4), c = c0 + (px & 15);
        bool ok = ((unsigned)r < 224u) && ((unsigned)c < 224u);
        int rr = ok ? r : 0, cl = ok ? c : 0;
        const void* src = g_in_h + ((((size_t)(n * 224 + rr)) * 224 + cl) * 256
                                    + cc * 16 + half * 8);
        uint32_t dst = aBase + (uint32_t)px * 32u
                     + (uint32_t)((half ^ ((px >> 2) & 1)) << 4);
        cpasync16(dst, src, ok ? 16 : 0);
    }
    // W: 2304 ops (576 rows x 2 halves, hi & lo arrays)
    #pragma unroll
    for (int k = 0; k < 9; k++) {
        int i = tid + (k << 8);
        int arr = (i >= 1152) ? 1 : 0;
        int j = i - arr * 1152;
        int row = j >> 1, half = j & 1;
        int pos = row >> 6, fl = row & 63;
        const __half* gsrc = arr ? g_wt_l : g_wt_h;
        const void* src = gsrc + (((size_t)(pos * 256 + fq * 64 + fl)) << 8)
                        + cc * 16 + half * 8;
        uint32_t dst = wBase + (uint32_t)arr * W_LO + (uint32_t)row * 32u
                     + (uint32_t)((half ^ ((row >> 2) & 1)) << 4);
        cpasync16(dst, src);
    }
}

__global__ void __launch_bounds__(256, 2)
conv_kernel(const float* __restrict__ bias, float* __restrict__ out)
{
    const int tile = blockIdx.x;
    const int fq   = blockIdx.y;         // 0..3 -> 64 F channels
    const int n = tile >> 8, bi = (tile >> 4) & 15, bj = tile & 15;
    const int tid = threadIdx.x;

    if (!g_active[tile]) {
        float4 z = make_float4(0.f, 0.f, 0.f, 0.f);
        for (int i = tid; i < 196 * 16; i += 256) {
            int px = i >> 4, q = i & 15;
            int oy = px / 14, ox = px - oy * 14;
            size_t o = (((size_t)(n * 224 + bi * 14 + oy)) * 224 + bj * 14 + ox) * 256
                       + fq * 64 + q * 4;
            *reinterpret_cast<float4*>(out + o) = z;
        }
        return;
    }

    extern __shared__ char sm[];
    const uint32_t sb = smem_to_u32(sm);

    const int l   = tid & 31;
    const int wid = tid >> 5;
    const int wm  = wid >> 2;            // 0..1 : M half (112 rows)
    const int wn  = wid & 3;             // 0..3 : 16-F slice within 64

    const int ra0   = wm * 112 + (l & 15);
    const int ahalf = l >> 4;
    const int rw0   = wn * 16 + ((l >> 4) & 1) * 8 + (l & 7);
    const uint32_t woff = (uint32_t)rw0 * 32u
        + (uint32_t)(((((l >> 3) & 1)) ^ ((rw0 >> 2) & 1)) << 4);

    const int r0 = bi * 14 - 1;
    const int c0 = bj * 14 - 1;

    // zero the pad rows (rows 256-257, 64B) in both A stages
    if (tid < 32) {
        int s = tid >> 4;
        *reinterpret_cast<uint32_t*>(sm + OFF_A + s * A_STAGE
                                     + 8192 + (tid & 15) * 4) = 0;
    }

    const uint32_t aS[2] = { sb + OFF_A, sb + OFF_A + A_STAGE };
    const uint32_t wS[2] = { sb + OFF_W, sb + OFF_W + W_STAGE };

    float acc[7][8];
    #pragma unroll
    for (int t = 0; t < 7; t++)
        #pragma unroll
        for (int j = 0; j < 8; j++) acc[t][j] = 0.f;

    // prologue: stage 0
    issue_stage(aS[0], wS[0], tid, n, r0, c0, fq, 0);
    asm volatile("cp.async.commit_group;\n" ::: "memory");

    for (int cc = 0; cc < 16; cc++) {
        const int p = cc & 1;
        asm volatile("cp.async.wait_group 0;\n" ::: "memory");
        __syncthreads();
        if (cc < 15) {
            issue_stage(aS[p ^ 1], wS[p ^ 1], tid, n, r0, c0, fq, cc + 1);
            asm volatile("cp.async.commit_group;\n" ::: "memory");
        }

        const uint32_t aB = aS[p];
        const uint32_t wB = wS[p];
        #pragma unroll 1
        for (int pos = 0; pos < 9; pos++) {
            const int ky = pos / 3, kx = pos - ky * 3;
            const int ra = ra0 + ky * 16 + kx;
            const uint32_t aaddr = aB + (uint32_t)ra * 32u
                + (uint32_t)((ahalf ^ ((ra >> 2) & 1)) << 4);
            const uint32_t wbase = wB + (uint32_t)pos * 2048u;

            uint32_t wh[4], wl[4];
            ldsm4(wh, wbase + woff);
            ldsm4(wl, wbase + W_LO + woff);

            uint32_t a[7][4];
            #pragma unroll
            for (int t = 0; t < 7; t++)
                ldsm4(a[t], aaddr + (uint32_t)t * 512u);
            #pragma unroll
            for (int t = 0; t < 7; t++) {
                mma16816(acc[t],     a[t], wh);
                mma16816(acc[t] + 4, a[t], wh + 2);
            }
            #pragma unroll
            for (int t = 0; t < 7; t++) {
                mma16816(acc[t],     a[t], wl);
                mma16816(acc[t] + 4, a[t], wl + 2);
            }
        }
    }

    // ---- epilogue: bias + relu + store ----
    const int f0 = fq * 64 + wn * 16 + (l & 3) * 2;
    const float b00 = bias[f0],     b01 = bias[f0 + 1];
    const float b10 = bias[f0 + 8], b11 = bias[f0 + 9];

    #pragma unroll
    for (int t = 0; t < 7; t++) {
        int m_lo = wm * 112 + t * 16 + (l >> 2);
        #pragma unroll
        for (int h = 0; h < 2; h++) {
            int m = m_lo + h * 8;
            int oy = m >> 4, ox = m & 15;
            if (ox < 14) {
                float* p = out + (((size_t)(n * 224 + bi * 14 + oy)) * 224
                                  + bj * 14 + ox) * 256 + f0;
                float2 v0, v1;
                v0.x = fmaxf(acc[t][h * 2 + 0] + b00, 0.f);
                v0.y = fmaxf(acc[t][h * 2 + 1] + b01, 0.f);
                v1.x = fmaxf(acc[t][h * 2 + 4] + b10, 0.f);
                v1.y = fmaxf(acc[t][h * 2 + 5] + b11, 0.f);
                *reinterpret_cast<float2*>(p) = v0;
                *reinterpret_cast<float2*>(p + 8) = v1;
            }
        }
    }
}

extern "C" void kernel_launch(void* const* d_in, const int* in_sizes, int n_in,
                              void* d_out, int out_size) {
    const float* inputs = (const float*)d_in[0];
    const float* mask   = (const float*)d_in[1];
    const float* kernel = (const float*)d_in[2];
    const float* bias   = (const float*)d_in[3];
    float* out = (float*)d_out;

    cudaFuncSetAttribute(conv_kernel, cudaFuncAttributeMaxDynamicSharedMemorySize, SMEM_DYN);

    prep_kernel<<<9472, 256>>>(inputs, mask, kernel);
    dim3 grid(NTILES, 4);
    conv_kernel<<<grid, 256, SMEM_DYN>>>(bias, out);
}

// round 11
// speedup vs baseline: 2.5564x; 1.6000x over previous
#include <cuda_runtime.h>
#include <cuda_fp16.h>
#include <cstdint>

#define NTILES 1024

__device__ int g_active[NTILES];
__device__ __align__(16) __half g_wt_h[9 * 256 * 256];        // [pos][f][c] fp16
__device__ __align__(16) __half g_in_h[4 * 224 * 224 * 256];  // input fp16

// ---------------- helpers ----------------
__device__ __forceinline__ uint32_t smem_to_u32(const void* p) {
    uint32_t a;
    asm("{ .reg .u64 t; cvta.to.shared.u64 t, %1; cvt.u32.u64 %0, t; }" : "=r"(a) : "l"(p));
    return a;
}
__device__ __forceinline__ void ldsm4(uint32_t* r, uint32_t addr) {
    asm volatile("ldmatrix.sync.aligned.m8n8.x4.shared.b16 {%0,%1,%2,%3}, [%4];"
                 : "=r"(r[0]), "=r"(r[1]), "=r"(r[2]), "=r"(r[3]) : "r"(addr));
}
__device__ __forceinline__ void mma16816(float* d, const uint32_t* a, const uint32_t* b) {
    asm volatile(
        "mma.sync.aligned.m16n8k16.row.col.f32.f16.f16.f32 "
        "{%0,%1,%2,%3}, {%4,%5,%6,%7}, {%8,%9}, {%0,%1,%2,%3};"
        : "+f"(d[0]), "+f"(d[1]), "+f"(d[2]), "+f"(d[3])
        : "r"(a[0]), "r"(a[1]), "r"(a[2]), "r"(a[3]), "r"(b[0]), "r"(b[1]));
}
__device__ __forceinline__ void cpasync16(uint32_t dst, const void* src, int sz) {
    asm volatile("cp.async.cg.shared.global [%0], [%1], 16, %2;\n"
                 :: "r"(dst), "l"(src), "r"(sz) : "memory");
}
__device__ __forceinline__ void cpasync16(uint32_t dst, const void* src) {
    asm volatile("cp.async.cg.shared.global [%0], [%1], 16;\n"
                 :: "r"(dst), "l"(src) : "memory");
}

// ---------------- Stage 0 (fused prep) ----------------
__global__ void __launch_bounds__(256)
prep_kernel(const float* __restrict__ in,
            const float* __restrict__ mask,
            const float* __restrict__ wt)
{
    const int b = blockIdx.x;
    const int tid = threadIdx.x;
    if (b < 1024) {
        int n = b >> 8, bi = (b >> 4) & 15, bj = b & 15;
        int j = tid >> 4, i = tid & 15;
        int r = bi * 14 + j - 1;
        int c = bj * 14 + i - 1;
        float v = 0.0f;
        if (r >= 0 && r < 224 && c >= 0 && c < 224) v = mask[(n * 224 + r) * 224 + c];
        __shared__ double s[256];
        s[tid] = (double)v;
        __syncthreads();
        for (int off = 128; off > 0; off >>= 1) {
            if (tid < off) s[tid] += s[tid + off];
            __syncthreads();
        }
        if (tid == 0) g_active[b] = (s[0] > 128.0) ? 1 : 0;
    } else if (b < 1024 + 2304) {
        // weight transpose: [pos][c][f] -> [pos][f][c] fp16
        int bb = b - 1024;
        int pos = bb >> 8, f = bb & 255, c = tid;
        float x = wt[((size_t)((pos << 8) | c)) * 256 + f];
        g_wt_h[((size_t)((pos << 8) | f)) * 256 + c] = __float2half_rn(x);
    } else {
        // input fp32 -> fp16, vectorized
        size_t idx = (size_t)(b - 3328) * 256 + tid;
        const float4* in4 = reinterpret_cast<const float4*>(in);
        const size_t total4 = 12845056ull;
        const size_t stride = 6144ull * 256ull;
        for (size_t i = idx; i < total4; i += stride) {
            float4 v = in4[i];
            uint2 hp;
            hp.x = (uint32_t)__half_as_ushort(__float2half_rn(v.x))
                 | ((uint32_t)__half_as_ushort(__float2half_rn(v.y)) << 16);
            hp.y = (uint32_t)__half_as_ushort(__float2half_rn(v.z))
                 | ((uint32_t)__half_as_ushort(__float2half_rn(v.w)) << 16);
            *reinterpret_cast<uint2*>(g_in_h + 4 * i) = hp;
        }
    }
}

// ---------------- Stage 1: pipelined implicit-GEMM conv, N=64/CTA, 1-pass ----
// A per stage: 258 rows x 32B = 8256 B
// W per stage: 9 pos x 64 f rows x 32B = 18432 B
// XOR swizzle: byte(row, half) = row*32 + ((half ^ ((row>>2)&1)) << 4)
#define OFF_A   0u
#define A_STAGE 8256u
#define OFF_W   16512u
#define W_STAGE 18432u
#define SMEM_DYN 53376

__device__ __forceinline__ void issue_stage(uint32_t aBase, uint32_t wBase,
                                            int tid, int n, int r0, int c0,
                                            int fq, int cc)
{
    // A: 512 ops (256 px x 2 halves)
    #pragma unroll
    for (int k = 0; k < 2; k++) {
        int i = tid + (k << 8);
        int px   = i >> 1;
        int half = i & 1;
        int r = r0 + (px >> 4), c = c0 + (px & 15);
        bool ok = ((unsigned)r < 224u) && ((unsigned)c < 224u);
        int rr = ok ? r : 0, cl = ok ? c : 0;
        const void* src = g_in_h + ((((size_t)(n * 224 + rr)) * 224 + cl) * 256
                                    + cc * 16 + half * 8);
        uint32_t dst = aBase + (uint32_t)px * 32u
                     + (uint32_t)((half ^ ((px >> 2) & 1)) << 4);
        cpasync16(dst, src, ok ? 16 : 0);
    }
    // W: 1152 ops (576 rows x 2 halves)
    #pragma unroll
    for (int k = 0; k < 5; k++) {
        int i = tid + (k << 8);
        if (i < 1152) {
            int row = i >> 1, half = i & 1;
            int pos = row >> 6, fl = row & 63;
            const void* src = g_wt_h + (((size_t)(pos * 256 + fq * 64 + fl)) << 8)
                            + cc * 16 + half * 8;
            uint32_t dst = wBase + (uint32_t)row * 32u
                         + (uint32_t)((half ^ ((row >> 2) & 1)) << 4);
            cpasync16(dst, src);
        }
    }
}

__global__ void __launch_bounds__(256, 2)
conv_kernel(const float* __restrict__ bias, float* __restrict__ out)
{
    const int tile = blockIdx.x;
    const int fq   = blockIdx.y;         // 0..3 -> 64 F channels
    const int n = tile >> 8, bi = (tile >> 4) & 15, bj = tile & 15;
    const int tid = threadIdx.x;

    if (!g_active[tile]) {
        float4 z = make_float4(0.f, 0.f, 0.f, 0.f);
        for (int i = tid; i < 196 * 16; i += 256) {
            int px = i >> 4, q = i & 15;
            int oy = px / 14, ox = px - oy * 14;
            size_t o = (((size_t)(n * 224 + bi * 14 + oy)) * 224 + bj * 14 + ox) * 256
                       + fq * 64 + q * 4;
            *reinterpret_cast<float4*>(out + o) = z;
        }
        return;
    }

    extern __shared__ char sm[];
    const uint32_t sb = smem_to_u32(sm);

    const int l   = tid & 31;
    const int wid = tid >> 5;
    const int wm  = wid >> 2;            // 0..1 : M half (112 rows)
    const int wn  = wid & 3;             // 0..3 : 16-F slice within 64

    const int ra0   = wm * 112 + (l & 15);
    const int ahalf = l >> 4;
    const int rw0   = wn * 16 + ((l >> 4) & 1) * 8 + (l & 7);
    const uint32_t woff = (uint32_t)rw0 * 32u
        + (uint32_t)(((((l >> 3) & 1)) ^ ((rw0 >> 2) & 1)) << 4);

    const int r0 = bi * 14 - 1;
    const int c0 = bj * 14 - 1;

    // zero the pad rows (rows 256-257, 64B) in both A stages
    if (tid < 32) {
        int s = tid >> 4;
        *reinterpret_cast<uint32_t*>(sm + OFF_A + s * A_STAGE
                                     + 8192 + (tid & 15) * 4) = 0;
    }

    const uint32_t aS[2] = { sb + OFF_A, sb + OFF_A + A_STAGE };
    const uint32_t wS[2] = { sb + OFF_W, sb + OFF_W + W_STAGE };

    float acc[7][8];
    #pragma unroll
    for (int t = 0; t < 7; t++)
        #pragma unroll
        for (int j = 0; j < 8; j++) acc[t][j] = 0.f;

    // prologue: stage 0
    issue_stage(aS[0], wS[0], tid, n, r0, c0, fq, 0);
    asm volatile("cp.async.commit_group;\n" ::: "memory");

    for (int cc = 0; cc < 16; cc++) {
        const int p = cc & 1;
        asm volatile("cp.async.wait_group 0;\n" ::: "memory");
        __syncthreads();
        if (cc < 15) {
            issue_stage(aS[p ^ 1], wS[p ^ 1], tid, n, r0, c0, fq, cc + 1);
            asm volatile("cp.async.commit_group;\n" ::: "memory");
        }

        const uint32_t aB = aS[p];
        const uint32_t wB = wS[p];
        #pragma unroll 1
        for (int pos = 0; pos < 9; pos++) {
            const int ky = pos / 3, kx = pos - ky * 3;
            const int ra = ra0 + ky * 16 + kx;
            const uint32_t aaddr = aB + (uint32_t)ra * 32u
                + (uint32_t)((ahalf ^ ((ra >> 2) & 1)) << 4);

            uint32_t wh[4];
            ldsm4(wh, wB + (uint32_t)pos * 2048u + woff);

            uint32_t a[7][4];
            #pragma unroll
            for (int t = 0; t < 7; t++)
                ldsm4(a[t], aaddr + (uint32_t)t * 512u);
            #pragma unroll
            for (int t = 0; t < 7; t++) {
                mma16816(acc[t],     a[t], wh);
                mma16816(acc[t] + 4, a[t], wh + 2);
            }
        }
    }

    // ---- epilogue: bias + relu + store ----
    const int f0 = fq * 64 + wn * 16 + (l & 3) * 2;
    const float b00 = bias[f0],     b01 = bias[f0 + 1];
    const float b10 = bias[f0 + 8], b11 = bias[f0 + 9];

    #pragma unroll
    for (int t = 0; t < 7; t++) {
        int m_lo = wm * 112 + t * 16 + (l >> 2);
        #pragma unroll
        for (int h = 0; h < 2; h++) {
            int m = m_lo + h * 8;
            int oy = m >> 4, ox = m & 15;
            if (ox < 14) {
                float* p = out + (((size_t)(n * 224 + bi * 14 + oy)) * 224
                                  + bj * 14 + ox) * 256 + f0;
                float2 v0, v1;
                v0.x = fmaxf(acc[t][h * 2 + 0] + b00, 0.f);
                v0.y = fmaxf(acc[t][h * 2 + 1] + b01, 0.f);
                v1.x = fmaxf(acc[t][h * 2 + 4] + b10, 0.f);
                v1.y = fmaxf(acc[t][h * 2 + 5] + b11, 0.f);
                *reinterpret_cast<float2*>(p) = v0;
                *reinterpret_cast<float2*>(p + 8) = v1;
            }
        }
    }
}

extern "C" void kernel_launch(void* const* d_in, const int* in_sizes, int n_in,
                              void* d_out, int out_size) {
    const float* inputs = (const float*)d_in[0];
    const float* mask   = (const float*)d_in[1];
    const float* kernel = (const float*)d_in[2];
    const float* bias   = (const float*)d_in[3];
    float* out = (float*)d_out;

    cudaFuncSetAttribute(conv_kernel, cudaFuncAttributeMaxDynamicSharedMemorySize, SMEM_DYN);

    prep_kernel<<<9472, 256>>>(inputs, mask, kernel);
    dim3 grid(NTILES, 4);
    conv_kernel<<<grid, 256, SMEM_DYN>>>(bias, out);
}

// round 13
// speedup vs baseline: 2.8462x; 1.1133x over previous
#include <cuda_runtime.h>
#include <cuda_fp16.h>
#include <cstdint>

#define NTILES 1024

__device__ int g_active[NTILES];
__device__ __align__(16) __half g_wt_h[9 * 256 * 256];        // [pos][f][c] fp16
__device__ __align__(16) __half g_in_h[4 * 224 * 224 * 256];  // input fp16

// ---------------- helpers ----------------
__device__ __forceinline__ uint32_t smem_to_u32(const void* p) {
    uint32_t a;
    asm("{ .reg .u64 t; cvta.to.shared.u64 t, %1; cvt.u32.u64 %0, t; }" : "=r"(a) : "l"(p));
    return a;
}
__device__ __forceinline__ void ldsm4(uint32_t* r, uint32_t addr) {
    asm volatile("ldmatrix.sync.aligned.m8n8.x4.shared.b16 {%0,%1,%2,%3}, [%4];"
                 : "=r"(r[0]), "=r"(r[1]), "=r"(r[2]), "=r"(r[3]) : "r"(addr));
}
__device__ __forceinline__ void mma16816(float* d, const uint32_t* a, const uint32_t* b) {
    asm volatile(
        "mma.sync.aligned.m16n8k16.row.col.f32.f16.f16.f32 "
        "{%0,%1,%2,%3}, {%4,%5,%6,%7}, {%8,%9}, {%0,%1,%2,%3};"
        : "+f"(d[0]), "+f"(d[1]), "+f"(d[2]), "+f"(d[3])
        : "r"(a[0]), "r"(a[1]), "r"(a[2]), "r"(a[3]), "r"(b[0]), "r"(b[1]));
}
__device__ __forceinline__ void cpasync16(uint32_t dst, const void* src, int sz) {
    asm volatile("cp.async.cg.shared.global [%0], [%1], 16, %2;\n"
                 :: "r"(dst), "l"(src), "r"(sz) : "memory");
}
__device__ __forceinline__ void cpasync16(uint32_t dst, const void* src) {
    asm volatile("cp.async.cg.shared.global [%0], [%1], 16;\n"
                 :: "r"(dst), "l"(src) : "memory");
}

// ---------------- Stage 0 (fused prep) ----------------
__global__ void __launch_bounds__(256)
prep_kernel(const float* __restrict__ in,
            const float* __restrict__ mask,
            const float* __restrict__ wt)
{
    const int b = blockIdx.x;
    const int tid = threadIdx.x;
    if (b < 1024) {
        int n = b >> 8, bi = (b >> 4) & 15, bj = b & 15;
        int j = tid >> 4, i = tid & 15;
        int r = bi * 14 + j - 1;
        int c = bj * 14 + i - 1;
        float v = 0.0f;
        if (r >= 0 && r < 224 && c >= 0 && c < 224) v = mask[(n * 224 + r) * 224 + c];
        __shared__ double s[256];
        s[tid] = (double)v;
        __syncthreads();
        for (int off = 128; off > 0; off >>= 1) {
            if (tid < off) s[tid] += s[tid + off];
            __syncthreads();
        }
        if (tid == 0) g_active[b] = (s[0] > 128.0) ? 1 : 0;
    } else if (b < 1024 + 2304) {
        // weight transpose: [pos][c][f] -> [pos][f][c] fp16
        int bb = b - 1024;
        int pos = bb >> 8, f = bb & 255, c = tid;
        float x = wt[((size_t)((pos << 8) | c)) * 256 + f];
        g_wt_h[((size_t)((pos << 8) | f)) * 256 + c] = __float2half_rn(x);
    } else {
        // input fp32 -> fp16, vectorized
        size_t idx = (size_t)(b - 3328) * 256 + tid;
        const float4* in4 = reinterpret_cast<const float4*>(in);
        const size_t total4 = 12845056ull;
        const size_t stride = 6144ull * 256ull;
        for (size_t i = idx; i < total4; i += stride) {
            float4 v = in4[i];
            uint2 hp;
            hp.x = (uint32_t)__half_as_ushort(__float2half_rn(v.x))
                 | ((uint32_t)__half_as_ushort(__float2half_rn(v.y)) << 16);
            hp.y = (uint32_t)__half_as_ushort(__float2half_rn(v.z))
                 | ((uint32_t)__half_as_ushort(__float2half_rn(v.w)) << 16);
            *reinterpret_cast<uint2*>(g_in_h + 4 * i) = hp;
        }
    }
}

// ---------------- Stage 1: pipelined implicit-GEMM conv, N=64/CTA, 1-pass ----
// A per stage: 258 rows x 32B = 8256 B
// W per stage: 9 pos x 64 f rows x 32B = 18432 B
// XOR swizzle: byte(row, half) = row*32 + ((half ^ ((row>>2)&1)) << 4)
#define OFF_A   0u
#define A_STAGE 8256u
#define OFF_W   16512u
#define W_STAGE 18432u
#define SMEM_DYN 53376

__device__ __forceinline__ void issue_stage(uint32_t aBase, uint32_t wBase,
                                            int tid, int n, int r0, int c0,
                                            int fq, int cc)
{
    // A: 512 ops (256 px x 2 halves)
    #pragma unroll
    for (int k = 0; k < 2; k++) {
        int i = tid + (k << 8);
        int px   = i >> 1;
        int half = i & 1;
        int r = r0 + (px >> 4), c = c0 + (px & 15);
        bool ok = ((unsigned)r < 224u) && ((unsigned)c < 224u);
        int rr = ok ? r : 0, cl = ok ? c : 0;
        const void* src = g_in_h + ((((size_t)(n * 224 + rr)) * 224 + cl) * 256
                                    + cc * 16 + half * 8);
        uint32_t dst = aBase + (uint32_t)px * 32u
                     + (uint32_t)((half ^ ((px >> 2) & 1)) << 4);
        cpasync16(dst, src, ok ? 16 : 0);
    }
    // W: 1152 ops (576 rows x 2 halves)
    #pragma unroll
    for (int k = 0; k < 5; k++) {
        int i = tid + (k << 8);
        if (i < 1152) {
            int row = i >> 1, half = i & 1;
            int pos = row >> 6, fl = row & 63;
            const void* src = g_wt_h + (((size_t)(pos * 256 + fq * 64 + fl)) << 8)
                            + cc * 16 + half * 8;
            uint32_t dst = wBase + (uint32_t)row * 32u
                         + (uint32_t)((half ^ ((row >> 2) & 1)) << 4);
            cpasync16(dst, src);
        }
    }
}

__global__ void __launch_bounds__(256, 2)
conv_kernel(const float* __restrict__ bias, float* __restrict__ out)
{
    const int tile = blockIdx.x;
    const int fq   = blockIdx.y;         // 0..3 -> 64 F channels
    const int n = tile >> 8, bi = (tile >> 4) & 15, bj = tile & 15;
    const int tid = threadIdx.x;

    if (!g_active[tile]) {
        float4 z = make_float4(0.f, 0.f, 0.f, 0.f);
        for (int i = tid; i < 196 * 16; i += 256) {
            int px = i >> 4, q = i & 15;
            int oy = px / 14, ox = px - oy * 14;
            size_t o = (((size_t)(n * 224 + bi * 14 + oy)) * 224 + bj * 14 + ox) * 256
                       + fq * 64 + q * 4;
            *reinterpret_cast<float4*>(out + o) = z;
        }
        return;
    }

    extern __shared__ char sm[];
    const uint32_t sb = smem_to_u32(sm);

    const int l   = tid & 31;
    const int wid = tid >> 5;
    const int wm  = wid >> 2;            // 0..1 : M half (112 rows)
    const int wn  = wid & 3;             // 0..3 : 16-F slice within 64

    const int ra0   = wm * 112 + (l & 15);
    const int ahalf = l >> 4;
    const int rw0   = wn * 16 + ((l >> 4) & 1) * 8 + (l & 7);
    const uint32_t woff = (uint32_t)rw0 * 32u
        + (uint32_t)(((((l >> 3) & 1)) ^ ((rw0 >> 2) & 1)) << 4);

    const int r0 = bi * 14 - 1;
    const int c0 = bj * 14 - 1;

    // zero the pad rows (rows 256-257, 64B) in both A stages
    if (tid < 32) {
        int s = tid >> 4;
        *reinterpret_cast<uint32_t*>(sm + OFF_A + s * A_STAGE
                                     + 8192 + (tid & 15) * 4) = 0;
    }

    const uint32_t aS[2] = { sb + OFF_A, sb + OFF_A + A_STAGE };
    const uint32_t wS[2] = { sb + OFF_W, sb + OFF_W + W_STAGE };

    float acc[7][8];
    #pragma unroll
    for (int t = 0; t < 7; t++)
        #pragma unroll
        for (int j = 0; j < 8; j++) acc[t][j] = 0.f;

    // prologue: stage 0
    issue_stage(aS[0], wS[0], tid, n, r0, c0, fq, 0);
    asm volatile("cp.async.commit_group;\n" ::: "memory");

    for (int cc = 0; cc < 16; cc++) {
        const int p = cc & 1;
        asm volatile("cp.async.wait_group 0;\n" ::: "memory");
        __syncthreads();
        if (cc < 15) {
            issue_stage(aS[p ^ 1], wS[p ^ 1], tid, n, r0, c0, fq, cc + 1);
            asm volatile("cp.async.commit_group;\n" ::: "memory");
        }

        const uint32_t aB = aS[p];
        const uint32_t wB = wS[p];
        // A-fragment reuse across ky: per kx load 9 tiles (rows ra0+kx+16t),
        // ky uses a[ky..ky+6] (row shift 16 == tile shift 1).
        #pragma unroll 1
        for (int kx = 0; kx < 3; kx++) {
            const int ra = ra0 + kx;
            const uint32_t aaddr = aB + (uint32_t)ra * 32u
                + (uint32_t)((ahalf ^ ((ra >> 2) & 1)) << 4);
            uint32_t a[9][4];
            #pragma unroll
            for (int t = 0; t < 9; t++)
                ldsm4(a[t], aaddr + (uint32_t)t * 512u);

            #pragma unroll
            for (int ky = 0; ky < 3; ky++) {
                uint32_t wh[4];
                ldsm4(wh, wB + (uint32_t)(ky * 3 + kx) * 2048u + woff);
                #pragma unroll
                for (int t = 0; t < 7; t++) {
                    mma16816(acc[t],     a[t + ky], wh);
                    mma16816(acc[t] + 4, a[t + ky], wh + 2);
                }
            }
        }
    }

    // ---- epilogue: bias + relu + store ----
    const int f0 = fq * 64 + wn * 16 + (l & 3) * 2;
    const float b00 = bias[f0],     b01 = bias[f0 + 1];
    const float b10 = bias[f0 + 8], b11 = bias[f0 + 9];

    #pragma unroll
    for (int t = 0; t < 7; t++) {
        int m_lo = wm * 112 + t * 16 + (l >> 2);
        #pragma unroll
        for (int h = 0; h < 2; h++) {
            int m = m_lo + h * 8;
            int oy = m >> 4, ox = m & 15;
            if (ox < 14) {
                float* p = out + (((size_t)(n * 224 + bi * 14 + oy)) * 224
                                  + bj * 14 + ox) * 256 + f0;
                float2 v0, v1;
                v0.x = fmaxf(acc[t][h * 2 + 0] + b00, 0.f);
                v0.y = fmaxf(acc[t][h * 2 + 1] + b01, 0.f);
                v1.x = fmaxf(acc[t][h * 2 + 4] + b10, 0.f);
                v1.y = fmaxf(acc[t][h * 2 + 5] + b11, 0.f);
                *reinterpret_cast<float2*>(p) = v0;
                *reinterpret_cast<float2*>(p + 8) = v1;
            }
        }
    }
}

extern "C" void kernel_launch(void* const* d_in, const int* in_sizes, int n_in,
                              void* d_out, int out_size) {
    const float* inputs = (const float*)d_in[0];
    const float* mask   = (const float*)d_in[1];
    const float* kernel = (const float*)d_in[2];
    const float* bias   = (const float*)d_in[3];
    float* out = (float*)d_out;

    cudaFuncSetAttribute(conv_kernel, cudaFuncAttributeMaxDynamicSharedMemorySize, SMEM_DYN);

    prep_kernel<<<9472, 256>>>(inputs, mask, kernel);
    dim3 grid(NTILES, 4);
    conv_kernel<<<grid, 256, SMEM_DYN>>>(bias, out);
}

// round 14
// speedup vs baseline: 2.9113x; 1.0229x over previous
#include <cuda_runtime.h>
#include <cuda_fp16.h>
#include <cstdint>

#define NTILES 1024

__device__ int g_active[NTILES];
__device__ __align__(16) __half g_wt_h[9 * 256 * 256];        // [pos][f][c] fp16
__device__ __align__(16) __half g_in_h[4 * 224 * 224 * 256];  // input fp16

// ---------------- helpers ----------------
__device__ __forceinline__ uint32_t smem_to_u32(const void* p) {
    uint32_t a;
    asm("{ .reg .u64 t; cvta.to.shared.u64 t, %1; cvt.u32.u64 %0, t; }" : "=r"(a) : "l"(p));
    return a;
}
__device__ __forceinline__ void ldsm4(uint32_t* r, uint32_t addr) {
    asm volatile("ldmatrix.sync.aligned.m8n8.x4.shared.b16 {%0,%1,%2,%3}, [%4];"
                 : "=r"(r[0]), "=r"(r[1]), "=r"(r[2]), "=r"(r[3]) : "r"(addr));
}
__device__ __forceinline__ void mma16816(float* d, const uint32_t* a, const uint32_t* b) {
    asm volatile(
        "mma.sync.aligned.m16n8k16.row.col.f32.f16.f16.f32 "
        "{%0,%1,%2,%3}, {%4,%5,%6,%7}, {%8,%9}, {%0,%1,%2,%3};"
        : "+f"(d[0]), "+f"(d[1]), "+f"(d[2]), "+f"(d[3])
        : "r"(a[0]), "r"(a[1]), "r"(a[2]), "r"(a[3]), "r"(b[0]), "r"(b[1]));
}
__device__ __forceinline__ void cpasync16(uint32_t dst, const void* src, int sz) {
    asm volatile("cp.async.cg.shared.global [%0], [%1], 16, %2;\n"
                 :: "r"(dst), "l"(src), "r"(sz) : "memory");
}
__device__ __forceinline__ void cpasync16(uint32_t dst, const void* src) {
    asm volatile("cp.async.cg.shared.global [%0], [%1], 16;\n"
                 :: "r"(dst), "l"(src) : "memory");
}

// ---------------- Stage 0 (fused prep) ----------------
__global__ void __launch_bounds__(256)
prep_kernel(const float* __restrict__ in,
            const float* __restrict__ mask,
            const float* __restrict__ wt)
{
    const int b = blockIdx.x;
    const int tid = threadIdx.x;
    if (b < 1024) {
        int n = b >> 8, bi = (b >> 4) & 15, bj = b & 15;
        int j = tid >> 4, i = tid & 15;
        int r = bi * 14 + j - 1;
        int c = bj * 14 + i - 1;
        float v = 0.0f;
        if (r >= 0 && r < 224 && c >= 0 && c < 224) v = mask[(n * 224 + r) * 224 + c];
        __shared__ double s[256];
        s[tid] = (double)v;
        __syncthreads();
        for (int off = 128; off > 0; off >>= 1) {
            if (tid < off) s[tid] += s[tid + off];
            __syncthreads();
        }
        if (tid == 0) g_active[b] = (s[0] > 128.0) ? 1 : 0;
    } else if (b < 1024 + 2304) {
        // weight transpose: [pos][c][f] -> [pos][f][c] fp16
        int bb = b - 1024;
        int pos = bb >> 8, f = bb & 255, c = tid;
        float x = wt[((size_t)((pos << 8) | c)) * 256 + f];
        g_wt_h[((size_t)((pos << 8) | f)) * 256 + c] = __float2half_rn(x);
    } else {
        // input fp32 -> fp16, vectorized
        size_t idx = (size_t)(b - 3328) * 256 + tid;
        const float4* in4 = reinterpret_cast<const float4*>(in);
        const size_t total4 = 12845056ull;
        const size_t stride = 6144ull * 256ull;
        for (size_t i = idx; i < total4; i += stride) {
            float4 v = in4[i];
            uint2 hp;
            hp.x = (uint32_t)__half_as_ushort(__float2half_rn(v.x))
                 | ((uint32_t)__half_as_ushort(__float2half_rn(v.y)) << 16);
            hp.y = (uint32_t)__half_as_ushort(__float2half_rn(v.z))
                 | ((uint32_t)__half_as_ushort(__float2half_rn(v.w)) << 16);
            *reinterpret_cast<uint2*>(g_in_h + 4 * i) = hp;
        }
    }
}

// ---------------- Stage 1: 3-stage pipelined implicit-GEMM conv, N=64/CTA ----
// Per stage (26688 B): A = 258 rows x 32B = 8256 B, then W = 576 rows x 32B = 18432 B
// XOR swizzle: byte(row, half) = row*32 + ((half ^ ((row>>2)&1)) << 4)
#define STAGE_SZ 26688u
#define W_OFF    8256u
#define NSTAGE   3
#define SMEM_DYN 80064

__device__ __forceinline__ void issue_stage(uint32_t stBase,
                                            int tid, int n, int r0, int c0,
                                            int fq, int cc)
{
    // A: 512 ops (256 px x 2 halves)
    #pragma unroll
    for (int k = 0; k < 2; k++) {
        int i = tid + (k << 8);
        int px   = i >> 1;
        int half = i & 1;
        int r = r0 + (px >> 4), c = c0 + (px & 15);
        bool ok = ((unsigned)r < 224u) && ((unsigned)c < 224u);
        int rr = ok ? r : 0, cl = ok ? c : 0;
        const void* src = g_in_h + ((((size_t)(n * 224 + rr)) * 224 + cl) * 256
                                    + cc * 16 + half * 8);
        uint32_t dst = stBase + (uint32_t)px * 32u
                     + (uint32_t)((half ^ ((px >> 2) & 1)) << 4);
        cpasync16(dst, src, ok ? 16 : 0);
    }
    // W: 1152 ops (576 rows x 2 halves)
    #pragma unroll
    for (int k = 0; k < 5; k++) {
        int i = tid + (k << 8);
        if (i < 1152) {
            int row = i >> 1, half = i & 1;
            int pos = row >> 6, fl = row & 63;
            const void* src = g_wt_h + (((size_t)(pos * 256 + fq * 64 + fl)) << 8)
                            + cc * 16 + half * 8;
            uint32_t dst = stBase + W_OFF + (uint32_t)row * 32u
                         + (uint32_t)((half ^ ((row >> 2) & 1)) << 4);
            cpasync16(dst, src);
        }
    }
}

__global__ void __launch_bounds__(256, 2)
conv_kernel(const float* __restrict__ bias, float* __restrict__ out)
{
    const int tile = blockIdx.x;
    const int fq   = blockIdx.y;         // 0..3 -> 64 F channels
    const int n = tile >> 8, bi = (tile >> 4) & 15, bj = tile & 15;
    const int tid = threadIdx.x;

    if (!g_active[tile]) {
        float4 z = make_float4(0.f, 0.f, 0.f, 0.f);
        for (int i = tid; i < 196 * 16; i += 256) {
            int px = i >> 4, q = i & 15;
            int oy = px / 14, ox = px - oy * 14;
            size_t o = (((size_t)(n * 224 + bi * 14 + oy)) * 224 + bj * 14 + ox) * 256
                       + fq * 64 + q * 4;
            *reinterpret_cast<float4*>(out + o) = z;
        }
        return;
    }

    extern __shared__ char sm[];
    const uint32_t sb = smem_to_u32(sm);

    const int l   = tid & 31;
    const int wid = tid >> 5;
    const int wm  = wid >> 2;            // 0..1 : M half (112 rows)
    const int wn  = wid & 3;             // 0..3 : 16-F slice within 64

    const int ra0   = wm * 112 + (l & 15);
    const int ahalf = l >> 4;
    const int rw0   = wn * 16 + ((l >> 4) & 1) * 8 + (l & 7);
    const uint32_t woff = (uint32_t)rw0 * 32u
        + (uint32_t)(((((l >> 3) & 1)) ^ ((rw0 >> 2) & 1)) << 4);

    const int r0 = bi * 14 - 1;
    const int c0 = bj * 14 - 1;

    // zero the A pad rows (rows 256-257, 64B) in all 3 stages
    if (tid < 48) {
        int s = tid >> 4;
        *reinterpret_cast<uint32_t*>(sm + s * STAGE_SZ + 8192 + (tid & 15) * 4) = 0;
    }

    float acc[7][8];
    #pragma unroll
    for (int t = 0; t < 7; t++)
        #pragma unroll
        for (int j = 0; j < 8; j++) acc[t][j] = 0.f;

    // prologue: issue stages 0 and 1
    issue_stage(sb, tid, n, r0, c0, fq, 0);
    asm volatile("cp.async.commit_group;\n" ::: "memory");
    issue_stage(sb + STAGE_SZ, tid, n, r0, c0, fq, 1);
    asm volatile("cp.async.commit_group;\n" ::: "memory");

    int sl = 0;                           // stage slot of cc
    for (int cc = 0; cc < 16; cc++) {
        if (cc < 15)
            asm volatile("cp.async.wait_group 1;\n" ::: "memory");
        else
            asm volatile("cp.async.wait_group 0;\n" ::: "memory");
        __syncthreads();
        if (cc < 14) {
            int sln = sl + 2; if (sln >= NSTAGE) sln -= NSTAGE;
            issue_stage(sb + (uint32_t)sln * STAGE_SZ, tid, n, r0, c0, fq, cc + 2);
            asm volatile("cp.async.commit_group;\n" ::: "memory");
        }

        const uint32_t stB = sb + (uint32_t)sl * STAGE_SZ;
        // A-fragment reuse across ky: per kx load 9 tiles (rows ra0+kx+16t),
        // ky uses a[ky..ky+6] (row shift 16 == tile shift 1).
        #pragma unroll 1
        for (int kx = 0; kx < 3; kx++) {
            const int ra = ra0 + kx;
            const uint32_t aaddr = stB + (uint32_t)ra * 32u
                + (uint32_t)((ahalf ^ ((ra >> 2) & 1)) << 4);
            uint32_t a[9][4];
            #pragma unroll
            for (int t = 0; t < 9; t++)
                ldsm4(a[t], aaddr + (uint32_t)t * 512u);

            #pragma unroll
            for (int ky = 0; ky < 3; ky++) {
                uint32_t wh[4];
                ldsm4(wh, stB + W_OFF + (uint32_t)(ky * 3 + kx) * 2048u + woff);
                #pragma unroll
                for (int t = 0; t < 7; t++) {
                    mma16816(acc[t],     a[t + ky], wh);
                    mma16816(acc[t] + 4, a[t + ky], wh + 2);
                }
            }
        }
        if (++sl >= NSTAGE) sl -= NSTAGE;
    }

    // ---- epilogue: bias + relu + store ----
    const int f0 = fq * 64 + wn * 16 + (l & 3) * 2;
    const float b00 = bias[f0],     b01 = bias[f0 + 1];
    const float b10 = bias[f0 + 8], b11 = bias[f0 + 9];

    #pragma unroll
    for (int t = 0; t < 7; t++) {
        int m_lo = wm * 112 + t * 16 + (l >> 2);
        #pragma unroll
        for (int h = 0; h < 2; h++) {
            int m = m_lo + h * 8;
            int oy = m >> 4, ox = m & 15;
            if (ox < 14) {
                float* p = out + (((size_t)(n * 224 + bi * 14 + oy)) * 224
                                  + bj * 14 + ox) * 256 + f0;
                float2 v0, v1;
                v0.x = fmaxf(acc[t][h * 2 + 0] + b00, 0.f);
                v0.y = fmaxf(acc[t][h * 2 + 1] + b01, 0.f);
                v1.x = fmaxf(acc[t][h * 2 + 4] + b10, 0.f);
                v1.y = fmaxf(acc[t][h * 2 + 5] + b11, 0.f);
                *reinterpret_cast<float2*>(p) = v0;
                *reinterpret_cast<float2*>(p + 8) = v1;
            }
        }
    }
}

extern "C" void kernel_launch(void* const* d_in, const int* in_sizes, int n_in,
                              void* d_out, int out_size) {
    const float* inputs = (const float*)d_in[0];
    const float* mask   = (const float*)d_in[1];
    const float* kernel = (const float*)d_in[2];
    const float* bias   = (const float*)d_in[3];
    float* out = (float*)d_out;

    cudaFuncSetAttribute(conv_kernel, cudaFuncAttributeMaxDynamicSharedMemorySize, SMEM_DYN);

    prep_kernel<<<9472, 256>>>(inputs, mask, kernel);
    dim3 grid(NTILES, 4);
    conv_kernel<<<grid, 256, SMEM_DYN>>>(bias, out);
}